// round 2
// baseline (speedup 1.0000x reference)
#include <cuda_runtime.h>

#define B_   4
#define C_   256
#define CR_  32
#define N_   4096
#define EPS_ 1e-5f
#define SCALE_ 0.17677669529663687f   // 1/sqrt(32)

// ---------------- scratch (device globals; no allocations) ----------------
__device__ float g_q [B_*CR_*N_];
__device__ float g_k [B_*CR_*N_];
__device__ float g_v [B_*C_*N_];
__device__ float g_ao[B_*C_*N_];
__device__ float g_y [B_*C_*N_];

// ---------------- f32x2 helpers ----------------
__device__ __forceinline__ unsigned long long pk2(float lo, float hi){
    unsigned long long r;
    asm("mov.b64 %0, {%1, %2};" : "=l"(r) : "f"(lo), "f"(hi));
    return r;
}
__device__ __forceinline__ void fma2(unsigned long long &d, unsigned long long a, unsigned long long b){
    asm("fma.rn.f32x2 %0, %1, %2, %0;" : "+l"(d) : "l"(a), "l"(b));
}
__device__ __forceinline__ float2 upk(unsigned long long v){
    float x, y;
    asm("mov.b64 {%0, %1}, %2;" : "=f"(x), "=f"(y) : "l"(v));
    return make_float2(x, y);
}

// ---------------- channel GEMM: Y[b,o,n] = sum_c W[o,c] * X[b,c,n] ----------------
// Block tile: 64 (o) x 64 (n), K chunk 16 (8 pairs). 256 threads, 4x4 microtile, f32x2.
__global__ __launch_bounds__(256) void gemm_wx(const float* __restrict__ W,
                                               const float* __restrict__ X,
                                               float* __restrict__ Y, int OC)
{
    __shared__ float2 ws2[8][68];   // [k2][o]   pairs over K
    __shared__ float2 xs2[8][68];   // [k2][n]
    int tid = threadIdx.x;
    int tn  = tid & 15, tm = tid >> 4;
    int n0  = blockIdx.x * 64;
    int o0  = blockIdx.y * 64;
    int b   = blockIdx.z;
    const float* Xb = X + (size_t)b * C_ * N_;

    unsigned long long acc[4][4];
#pragma unroll
    for (int i = 0; i < 4; i++)
#pragma unroll
        for (int j = 0; j < 4; j++) acc[i][j] = 0ull;   // (+0.f, +0.f)

    for (int kt = 0; kt < C_ / 16; kt++) {
        int c0 = kt * 16;
        // W tile (transposed into [k2][o]), zero-fill rows beyond OC
#pragma unroll
        for (int s = 0; s < 2; s++) {
            int u  = tid + 256 * s;          // 0..511
            int o  = u & 63, k2 = u >> 6;    // k2 in 0..7
            float w0 = 0.f, w1 = 0.f;
            if (o0 + o < OC) {
                const float* wr = W + (size_t)(o0 + o) * C_ + c0 + 2 * k2;
                w0 = wr[0]; w1 = wr[1];
            }
            ws2[k2][o] = make_float2(w0, w1);
        }
        // X tile
        if (tid < 128) {
            int k2 = tid >> 4, n4 = (tid & 15) * 4;
            const float* xr0 = Xb + (size_t)(c0 + 2 * k2) * N_ + n0 + n4;
            float4 fa = *(const float4*)xr0;
            float4 fb = *(const float4*)(xr0 + N_);
            xs2[k2][n4 + 0] = make_float2(fa.x, fb.x);
            xs2[k2][n4 + 1] = make_float2(fa.y, fb.y);
            xs2[k2][n4 + 2] = make_float2(fa.z, fb.z);
            xs2[k2][n4 + 3] = make_float2(fa.w, fb.w);
        }
        __syncthreads();
#pragma unroll
        for (int k2 = 0; k2 < 8; k2++) {
            unsigned long long a2[4], b2[4];
#pragma unroll
            for (int i = 0; i < 4; i++) a2[i] = *(const unsigned long long*)&ws2[k2][tm * 4 + i];
#pragma unroll
            for (int j = 0; j < 4; j++) b2[j] = *(const unsigned long long*)&xs2[k2][tn + 16 * j];
#pragma unroll
            for (int i = 0; i < 4; i++)
#pragma unroll
                for (int j = 0; j < 4; j++) fma2(acc[i][j], a2[i], b2[j]);
        }
        __syncthreads();
    }
#pragma unroll
    for (int i = 0; i < 4; i++) {
        int o = o0 + tm * 4 + i;
        if (o < OC) {
            float* yr = Y + ((size_t)b * OC + o) * N_ + n0;
#pragma unroll
            for (int j = 0; j < 4; j++) {
                float2 r = upk(acc[i][j]);
                yr[tn + 16 * j] = r.x + r.y;
            }
        }
    }
}

// ---------------- flash attention (no-max softmax; logits ~N(0,1)) ----------------
// Grid: (N/64 q-tiles, 2 channel halves, B). 256 threads, 2 CTAs/SM.
#define QT 64
#define JT 64
#define CH 128
#define ATTN_SMEM_FLOATS 25152   // = 2176+2176+4160+8320+8256+64

__global__ __launch_bounds__(256, 2) void attn_kernel()
{
    extern __shared__ float sm[];
    float*  qs   = sm;               // [32][68]
    float*  ks   = sm + 2176;        // [32][68]
    float*  ps   = sm + 4352;        // [64][65]  p[j][q]
    float2* vs2  = (float2*)(sm + 8512); // [64][65]  channel pairs
    float*  os   = sm + 16832;       // [64][129] O[q][c_local]
    float*  lsum = sm + 25088;       // [64]

    int tid = threadIdx.x;
    int q0  = blockIdx.x * QT;
    int c0  = blockIdx.y * CH;
    int b   = blockIdx.z;

    // load q tile: qs[c][q]
#pragma unroll
    for (int s = 0; s < 2; s++) {
        int u = tid + 256 * s;                 // 0..511
        int c = u >> 4, q4 = (u & 15) * 4;
        float4 f = *(const float4*)&g_q[((size_t)b * CR_ + c) * N_ + q0 + q4];
        *(float4*)&qs[c * 68 + q4] = f;
    }
    for (int i = tid; i < 64 * 129; i += 256) os[i] = 0.f;
    if (tid < 64) lsum[tid] = 0.f;
    __syncthreads();

    for (int jt = 0; jt < N_ / JT; jt++) {
        int j0 = jt * JT;
        // load k tile
#pragma unroll
        for (int s = 0; s < 2; s++) {
            int u = tid + 256 * s;
            int c = u >> 4, j4 = (u & 15) * 4;
            float4 f = *(const float4*)&g_k[((size_t)b * CR_ + c) * N_ + j0 + j4];
            *(float4*)&ks[c * 68 + j4] = f;
        }
        // load v tile as channel pairs: vs2[c2][j] = (v[2c2], v[2c2+1])
#pragma unroll
        for (int s = 0; s < 4; s++) {
            int u  = tid + 256 * s;             // 0..1023
            int c2 = u >> 4, j4 = (u & 15) * 4;
            const float* vr0 = &g_v[((size_t)b * C_ + c0 + 2 * c2) * N_ + j0 + j4];
            float4 fa = *(const float4*)vr0;
            float4 fb = *(const float4*)(vr0 + N_);
            vs2[c2 * 65 + j4 + 0] = make_float2(fa.x, fb.x);
            vs2[c2 * 65 + j4 + 1] = make_float2(fa.y, fb.y);
            vs2[c2 * 65 + j4 + 2] = make_float2(fa.z, fb.z);
            vs2[c2 * 65 + j4 + 3] = make_float2(fa.w, fb.w);
        }
        __syncthreads();

        // S = q^T k, then exp(scale*S) -> ps[j][q]
        {
            int tj = tid & 15, tq = tid >> 4;
            float s4[4][4];
#pragma unroll
            for (int i = 0; i < 4; i++)
#pragma unroll
                for (int j = 0; j < 4; j++) s4[i][j] = 0.f;
#pragma unroll 8
            for (int c = 0; c < CR_; c++) {
                float4 a  = *(const float4*)&qs[c * 68 + tq * 4];
                float4 bb = *(const float4*)&ks[c * 68 + tj * 4];
                float av[4] = {a.x, a.y, a.z, a.w};
                float bv[4] = {bb.x, bb.y, bb.z, bb.w};
#pragma unroll
                for (int i = 0; i < 4; i++)
#pragma unroll
                    for (int j = 0; j < 4; j++) s4[i][j] = fmaf(av[i], bv[j], s4[i][j]);
            }
#pragma unroll
            for (int j = 0; j < 4; j++)
#pragma unroll
                for (int i = 0; i < 4; i++)
                    ps[(tj * 4 + j) * 65 + tq * 4 + i] = __expf(s4[i][j] * SCALE_);
        }
        __syncthreads();

        // deterministic softmax denominators (2 warps)
        if (tid < 64) {
            float acc = 0.f;
#pragma unroll 8
            for (int j = 0; j < 64; j++) acc += ps[j * 65 + tid];
            lsum[tid] += acc;
        }

        // PV: O[q][c] += p[q,j] * v[c,j], f32x2 over channel pairs
        {
            int qg = tid & 7, cg2 = tid >> 3;   // qg: 8 q-rows (interleaved), cg2: 4 channels
            unsigned long long A[8][2];
#pragma unroll
            for (int qq = 0; qq < 8; qq++) { A[qq][0] = 0ull; A[qq][1] = 0ull; }
            const unsigned long long* vrow0 = (const unsigned long long*)&vs2[(cg2 * 2)     * 65];
            const unsigned long long* vrow1 = (const unsigned long long*)&vs2[(cg2 * 2 + 1) * 65];
#pragma unroll 4
            for (int j = 0; j < 64; j++) {
                unsigned long long v0 = vrow0[j];
                unsigned long long v1 = vrow1[j];
                const float* prow = &ps[j * 65 + qg];
#pragma unroll
                for (int qq = 0; qq < 8; qq++) {
                    float p = prow[8 * qq];
                    unsigned long long pp = pk2(p, p);
                    fma2(A[qq][0], pp, v0);
                    fma2(A[qq][1], pp, v1);
                }
            }
#pragma unroll
            for (int qq = 0; qq < 8; qq++) {
                int qrow = (qg + 8 * qq) * 129;
                float2 r0 = upk(A[qq][0]);
                float2 r1 = upk(A[qq][1]);
                os[qrow + 4 * cg2 + 0] += r0.x;
                os[qrow + 4 * cg2 + 1] += r0.y;
                os[qrow + 4 * cg2 + 2] += r1.x;
                os[qrow + 4 * cg2 + 3] += r1.y;
            }
        }
        __syncthreads();
    }

    if (tid < 64) lsum[tid] = 1.f / lsum[tid];
    __syncthreads();
    for (int idx = tid; idx < QT * CH; idx += 256) {
        int q = idx & 63, c = idx >> 6;
        g_ao[((size_t)b * C_ + c0 + c) * N_ + q0 + q] = os[q * 129 + c] * lsum[q];
    }
}

// ---------------- instance norm + residual ----------------
__global__ __launch_bounds__(256) void norm_kernel(const float* __restrict__ x1,
                                                   float* __restrict__ out)
{
    int row = blockIdx.x;                 // b*C + o
    const float* yr = g_y + (size_t)row * N_;
    const float* xr = x1  + (size_t)row * N_;
    float*       orow = out + (size_t)row * N_;
    int tid = threadIdx.x;

    float4 v[4];
    float s = 0.f, ss = 0.f;
#pragma unroll
    for (int k = 0; k < 4; k++) {
        v[k] = *(const float4*)&yr[(tid + 256 * k) * 4];
        s  += v[k].x + v[k].y + v[k].z + v[k].w;
        ss += v[k].x * v[k].x + v[k].y * v[k].y + v[k].z * v[k].z + v[k].w * v[k].w;
    }
#pragma unroll
    for (int o = 16; o; o >>= 1) {
        s  += __shfl_xor_sync(0xffffffffu, s,  o);
        ss += __shfl_xor_sync(0xffffffffu, ss, o);
    }
    __shared__ float rs[8], rss[8];
    __shared__ float stats[2];
    if ((tid & 31) == 0) { rs[tid >> 5] = s; rss[tid >> 5] = ss; }
    __syncthreads();
    if (tid < 32) {
        float a  = (tid < 8) ? rs[tid]  : 0.f;
        float b2 = (tid < 8) ? rss[tid] : 0.f;
#pragma unroll
        for (int o = 4; o; o >>= 1) {
            a  += __shfl_xor_sync(0xffffffffu, a,  o);
            b2 += __shfl_xor_sync(0xffffffffu, b2, o);
        }
        if (tid == 0) {
            float mean = a * (1.f / N_);
            float var  = b2 * (1.f / N_) - mean * mean;
            stats[0] = mean;
            stats[1] = rsqrtf(var + EPS_);
        }
    }
    __syncthreads();
    float mean = stats[0], inv = stats[1];
#pragma unroll
    for (int k = 0; k < 4; k++) {
        float4 x4 = *(const float4*)&xr[(tid + 256 * k) * 4];
        float4 o4;
        o4.x = (v[k].x - mean) * inv + x4.x;
        o4.y = (v[k].y - mean) * inv + x4.y;
        o4.z = (v[k].z - mean) * inv + x4.z;
        o4.w = (v[k].w - mean) * inv + x4.w;
        *(float4*)&orow[(tid + 256 * k) * 4] = o4;
    }
}

// ---------------- launcher ----------------
extern "C" void kernel_launch(void* const* d_in, const int* in_sizes, int n_in,
                              void* d_out, int out_size)
{
    (void)in_sizes; (void)n_in; (void)out_size;
    const float* x1 = (const float*)d_in[0];
    const float* x2 = (const float*)d_in[1];
    const float* wq = (const float*)d_in[2];
    const float* wk = (const float*)d_in[3];
    const float* wv = (const float*)d_in[4];
    const float* wp = (const float*)d_in[5];
    float* out = (float*)d_out;

    void *qp, *kp, *vp, *aop, *yp;
    cudaGetSymbolAddress(&qp,  g_q);
    cudaGetSymbolAddress(&kp,  g_k);
    cudaGetSymbolAddress(&vp,  g_v);
    cudaGetSymbolAddress(&aop, g_ao);
    cudaGetSymbolAddress(&yp,  g_y);

    cudaFuncSetAttribute(attn_kernel, cudaFuncAttributeMaxDynamicSharedMemorySize,
                         ATTN_SMEM_FLOATS * 4);

    dim3 thr(256);
    gemm_wx<<<dim3(N_/64, 1, B_), thr>>>(wq, x1, (float*)qp, CR_);
    gemm_wx<<<dim3(N_/64, 1, B_), thr>>>(wk, x2, (float*)kp, CR_);
    gemm_wx<<<dim3(N_/64, C_/64, B_), thr>>>(wv, x2, (float*)vp, C_);
    attn_kernel<<<dim3(N_/QT, C_/CH, B_), thr, ATTN_SMEM_FLOATS * 4>>>();
    gemm_wx<<<dim3(N_/64, C_/64, B_), thr>>>(wp, (const float*)aop, (float*)yp, C_);
    norm_kernel<<<B_*C_, thr>>>(x1, out);
}

// round 3
// speedup vs baseline: 1.0038x; 1.0038x over previous
#include <cuda_runtime.h>

#define B_   4
#define C_   256
#define CR_  32
#define N_   4096
#define EPS_ 1e-5f
#define SCALE_ 0.17677669529663687f   // 1/sqrt(32)

// ---------------- scratch (device globals; no allocations) ----------------
__device__ float g_q [B_*CR_*N_];
__device__ float g_k [B_*CR_*N_];
__device__ float g_v [B_*C_*N_];
__device__ float g_ao[B_*C_*N_];
__device__ float g_y [B_*C_*N_];

// ---------------- f32x2 helpers ----------------
__device__ __forceinline__ unsigned long long pk2(float lo, float hi){
    unsigned long long r;
    asm("mov.b64 %0, {%1, %2};" : "=l"(r) : "f"(lo), "f"(hi));
    return r;
}
__device__ __forceinline__ void fma2(unsigned long long &d, unsigned long long a, unsigned long long b){
    asm("fma.rn.f32x2 %0, %1, %2, %0;" : "+l"(d) : "l"(a), "l"(b));
}
__device__ __forceinline__ float2 upk(unsigned long long v){
    float x, y;
    asm("mov.b64 {%0, %1}, %2;" : "=f"(x), "=f"(y) : "l"(v));
    return make_float2(x, y);
}

// ---------------- channel GEMM: Y[b,o,n] = sum_c W[o,c] * X[b,c,n] ----------------
// Block tile: 64 (o) x 64 (n), K chunk 16 (8 pairs). 256 threads, 4x4 microtile, f32x2.
__global__ __launch_bounds__(256) void gemm_wx(const float* __restrict__ W,
                                               const float* __restrict__ X,
                                               float* __restrict__ Y, int OC)
{
    __shared__ float2 ws2[8][68];   // [k2][o]   pairs over K
    __shared__ float2 xs2[8][68];   // [k2][n]
    int tid = threadIdx.x;
    int tn  = tid & 15, tm = tid >> 4;
    int n0  = blockIdx.x * 64;
    int o0  = blockIdx.y * 64;
    int b   = blockIdx.z;
    const float* Xb = X + (size_t)b * C_ * N_;

    unsigned long long acc[4][4];
#pragma unroll
    for (int i = 0; i < 4; i++)
#pragma unroll
        for (int j = 0; j < 4; j++) acc[i][j] = 0ull;   // (+0.f, +0.f)

    for (int kt = 0; kt < C_ / 16; kt++) {
        int c0 = kt * 16;
        // W tile (transposed into [k2][o]), zero-fill rows beyond OC
#pragma unroll
        for (int s = 0; s < 2; s++) {
            int u  = tid + 256 * s;          // 0..511
            int o  = u & 63, k2 = u >> 6;    // k2 in 0..7
            float w0 = 0.f, w1 = 0.f;
            if (o0 + o < OC) {
                const float* wr = W + (size_t)(o0 + o) * C_ + c0 + 2 * k2;
                w0 = wr[0]; w1 = wr[1];
            }
            ws2[k2][o] = make_float2(w0, w1);
        }
        // X tile
        if (tid < 128) {
            int k2 = tid >> 4, n4 = (tid & 15) * 4;
            const float* xr0 = Xb + (size_t)(c0 + 2 * k2) * N_ + n0 + n4;
            float4 fa = *(const float4*)xr0;
            float4 fb = *(const float4*)(xr0 + N_);
            xs2[k2][n4 + 0] = make_float2(fa.x, fb.x);
            xs2[k2][n4 + 1] = make_float2(fa.y, fb.y);
            xs2[k2][n4 + 2] = make_float2(fa.z, fb.z);
            xs2[k2][n4 + 3] = make_float2(fa.w, fb.w);
        }
        __syncthreads();
#pragma unroll
        for (int k2 = 0; k2 < 8; k2++) {
            unsigned long long a2[4], b2[4];
#pragma unroll
            for (int i = 0; i < 4; i++) a2[i] = *(const unsigned long long*)&ws2[k2][tm * 4 + i];
#pragma unroll
            for (int j = 0; j < 4; j++) b2[j] = *(const unsigned long long*)&xs2[k2][tn + 16 * j];
#pragma unroll
            for (int i = 0; i < 4; i++)
#pragma unroll
                for (int j = 0; j < 4; j++) fma2(acc[i][j], a2[i], b2[j]);
        }
        __syncthreads();
    }
#pragma unroll
    for (int i = 0; i < 4; i++) {
        int o = o0 + tm * 4 + i;
        if (o < OC) {
            float* yr = Y + ((size_t)b * OC + o) * N_ + n0;
#pragma unroll
            for (int j = 0; j < 4; j++) {
                float2 r = upk(acc[i][j]);
                yr[tn + 16 * j] = r.x + r.y;
            }
        }
    }
}

// ---------------- flash attention (no-max softmax; logits ~N(0,1)) ----------------
// Grid: (N/64 q-tiles, 2 channel halves, B). 256 threads, 2 CTAs/SM.
#define QT 64
#define JT 64
#define CH 128
#define ATTN_SMEM_FLOATS 25152   // = 2176+2176+4160+8320+8256+64

__global__ __launch_bounds__(256, 2) void attn_kernel()
{
    extern __shared__ float sm[];
    float*  qs   = sm;               // [32][68]
    float*  ks   = sm + 2176;        // [32][68]
    float*  ps   = sm + 4352;        // [64][65]  p[j][q]
    float2* vs2  = (float2*)(sm + 8512); // [64][65]  channel pairs
    float*  os   = sm + 16832;       // [64][129] O[q][c_local]
    float*  lsum = sm + 25088;       // [64]

    int tid = threadIdx.x;
    int q0  = blockIdx.x * QT;
    int c0  = blockIdx.y * CH;
    int b   = blockIdx.z;

    // load q tile: qs[c][q]
#pragma unroll
    for (int s = 0; s < 2; s++) {
        int u = tid + 256 * s;                 // 0..511
        int c = u >> 4, q4 = (u & 15) * 4;
        float4 f = *(const float4*)&g_q[((size_t)b * CR_ + c) * N_ + q0 + q4];
        *(float4*)&qs[c * 68 + q4] = f;
    }
    for (int i = tid; i < 64 * 129; i += 256) os[i] = 0.f;
    if (tid < 64) lsum[tid] = 0.f;
    __syncthreads();

    for (int jt = 0; jt < N_ / JT; jt++) {
        int j0 = jt * JT;
        // load k tile
#pragma unroll
        for (int s = 0; s < 2; s++) {
            int u = tid + 256 * s;
            int c = u >> 4, j4 = (u & 15) * 4;
            float4 f = *(const float4*)&g_k[((size_t)b * CR_ + c) * N_ + j0 + j4];
            *(float4*)&ks[c * 68 + j4] = f;
        }
        // load v tile as channel pairs: vs2[c2][j] = (v[2c2], v[2c2+1])
#pragma unroll
        for (int s = 0; s < 4; s++) {
            int u  = tid + 256 * s;             // 0..1023
            int c2 = u >> 4, j4 = (u & 15) * 4;
            const float* vr0 = &g_v[((size_t)b * C_ + c0 + 2 * c2) * N_ + j0 + j4];
            float4 fa = *(const float4*)vr0;
            float4 fb = *(const float4*)(vr0 + N_);
            vs2[c2 * 65 + j4 + 0] = make_float2(fa.x, fb.x);
            vs2[c2 * 65 + j4 + 1] = make_float2(fa.y, fb.y);
            vs2[c2 * 65 + j4 + 2] = make_float2(fa.z, fb.z);
            vs2[c2 * 65 + j4 + 3] = make_float2(fa.w, fb.w);
        }
        __syncthreads();

        // S = q^T k, then exp(scale*S) -> ps[j][q]
        {
            int tj = tid & 15, tq = tid >> 4;
            float s4[4][4];
#pragma unroll
            for (int i = 0; i < 4; i++)
#pragma unroll
                for (int j = 0; j < 4; j++) s4[i][j] = 0.f;
#pragma unroll 8
            for (int c = 0; c < CR_; c++) {
                float4 a  = *(const float4*)&qs[c * 68 + tq * 4];
                float4 bb = *(const float4*)&ks[c * 68 + tj * 4];
                float av[4] = {a.x, a.y, a.z, a.w};
                float bv[4] = {bb.x, bb.y, bb.z, bb.w};
#pragma unroll
                for (int i = 0; i < 4; i++)
#pragma unroll
                    for (int j = 0; j < 4; j++) s4[i][j] = fmaf(av[i], bv[j], s4[i][j]);
            }
#pragma unroll
            for (int j = 0; j < 4; j++)
#pragma unroll
                for (int i = 0; i < 4; i++)
                    ps[(tj * 4 + j) * 65 + tq * 4 + i] = __expf(s4[i][j] * SCALE_);
        }
        __syncthreads();

        // deterministic softmax denominators (2 warps)
        if (tid < 64) {
            float acc = 0.f;
#pragma unroll 8
            for (int j = 0; j < 64; j++) acc += ps[j * 65 + tid];
            lsum[tid] += acc;
        }

        // PV: O[q][c] += p[q,j] * v[c,j], f32x2 over channel pairs
        {
            int qg = tid & 7, cg2 = tid >> 3;   // qg: 8 q-rows (interleaved), cg2: 4 channels
            unsigned long long A[8][2];
#pragma unroll
            for (int qq = 0; qq < 8; qq++) { A[qq][0] = 0ull; A[qq][1] = 0ull; }
            const unsigned long long* vrow0 = (const unsigned long long*)&vs2[(cg2 * 2)     * 65];
            const unsigned long long* vrow1 = (const unsigned long long*)&vs2[(cg2 * 2 + 1) * 65];
#pragma unroll 4
            for (int j = 0; j < 64; j++) {
                unsigned long long v0 = vrow0[j];
                unsigned long long v1 = vrow1[j];
                const float* prow = &ps[j * 65 + qg];
#pragma unroll
                for (int qq = 0; qq < 8; qq++) {
                    float p = prow[8 * qq];
                    unsigned long long pp = pk2(p, p);
                    fma2(A[qq][0], pp, v0);
                    fma2(A[qq][1], pp, v1);
                }
            }
#pragma unroll
            for (int qq = 0; qq < 8; qq++) {
                int qrow = (qg + 8 * qq) * 129;
                float2 r0 = upk(A[qq][0]);
                float2 r1 = upk(A[qq][1]);
                os[qrow + 4 * cg2 + 0] += r0.x;
                os[qrow + 4 * cg2 + 1] += r0.y;
                os[qrow + 4 * cg2 + 2] += r1.x;
                os[qrow + 4 * cg2 + 3] += r1.y;
            }
        }
        __syncthreads();
    }

    if (tid < 64) lsum[tid] = 1.f / lsum[tid];
    __syncthreads();
    for (int idx = tid; idx < QT * CH; idx += 256) {
        int q = idx & 63, c = idx >> 6;
        g_ao[((size_t)b * C_ + c0 + c) * N_ + q0 + q] = os[q * 129 + c] * lsum[q];
    }
}

// ---------------- instance norm + residual ----------------
__global__ __launch_bounds__(256) void norm_kernel(const float* __restrict__ x1,
                                                   float* __restrict__ out)
{
    int row = blockIdx.x;                 // b*C + o
    const float* yr = g_y + (size_t)row * N_;
    const float* xr = x1  + (size_t)row * N_;
    float*       orow = out + (size_t)row * N_;
    int tid = threadIdx.x;

    float4 v[4];
    float s = 0.f, ss = 0.f;
#pragma unroll
    for (int k = 0; k < 4; k++) {
        v[k] = *(const float4*)&yr[(tid + 256 * k) * 4];
        s  += v[k].x + v[k].y + v[k].z + v[k].w;
        ss += v[k].x * v[k].x + v[k].y * v[k].y + v[k].z * v[k].z + v[k].w * v[k].w;
    }
#pragma unroll
    for (int o = 16; o; o >>= 1) {
        s  += __shfl_xor_sync(0xffffffffu, s,  o);
        ss += __shfl_xor_sync(0xffffffffu, ss, o);
    }
    __shared__ float rs[8], rss[8];
    __shared__ float stats[2];
    if ((tid & 31) == 0) { rs[tid >> 5] = s; rss[tid >> 5] = ss; }
    __syncthreads();
    if (tid < 32) {
        float a  = (tid < 8) ? rs[tid]  : 0.f;
        float b2 = (tid < 8) ? rss[tid] : 0.f;
#pragma unroll
        for (int o = 4; o; o >>= 1) {
            a  += __shfl_xor_sync(0xffffffffu, a,  o);
            b2 += __shfl_xor_sync(0xffffffffu, b2, o);
        }
        if (tid == 0) {
            float mean = a * (1.f / N_);
            float var  = b2 * (1.f / N_) - mean * mean;
            stats[0] = mean;
            stats[1] = rsqrtf(var + EPS_);
        }
    }
    __syncthreads();
    float mean = stats[0], inv = stats[1];
#pragma unroll
    for (int k = 0; k < 4; k++) {
        float4 x4 = *(const float4*)&xr[(tid + 256 * k) * 4];
        float4 o4;
        o4.x = (v[k].x - mean) * inv + x4.x;
        o4.y = (v[k].y - mean) * inv + x4.y;
        o4.z = (v[k].z - mean) * inv + x4.z;
        o4.w = (v[k].w - mean) * inv + x4.w;
        *(float4*)&orow[(tid + 256 * k) * 4] = o4;
    }
}

// ---------------- launcher ----------------
extern "C" void kernel_launch(void* const* d_in, const int* in_sizes, int n_in,
                              void* d_out, int out_size)
{
    (void)in_sizes; (void)n_in; (void)out_size;
    const float* x1 = (const float*)d_in[0];
    const float* x2 = (const float*)d_in[1];
    const float* wq = (const float*)d_in[2];
    const float* wk = (const float*)d_in[3];
    const float* wv = (const float*)d_in[4];
    const float* wp = (const float*)d_in[5];
    float* out = (float*)d_out;

    void *qp, *kp, *vp, *aop, *yp;
    cudaGetSymbolAddress(&qp,  g_q);
    cudaGetSymbolAddress(&kp,  g_k);
    cudaGetSymbolAddress(&vp,  g_v);
    cudaGetSymbolAddress(&aop, g_ao);
    cudaGetSymbolAddress(&yp,  g_y);

    cudaFuncSetAttribute(attn_kernel, cudaFuncAttributeMaxDynamicSharedMemorySize,
                         ATTN_SMEM_FLOATS * 4);

    dim3 thr(256);
    gemm_wx<<<dim3(N_/64, 1, B_), thr>>>(wq, x1, (float*)qp, CR_);
    gemm_wx<<<dim3(N_/64, 1, B_), thr>>>(wk, x2, (float*)kp, CR_);
    gemm_wx<<<dim3(N_/64, C_/64, B_), thr>>>(wv, x2, (float*)vp, C_);
    attn_kernel<<<dim3(N_/QT, C_/CH, B_), thr, ATTN_SMEM_FLOATS * 4>>>();
    gemm_wx<<<dim3(N_/64, C_/64, B_), thr>>>(wp, (const float*)aop, (float*)yp, C_);
    norm_kernel<<<B_*C_, thr>>>(x1, out);
}

// round 5
// speedup vs baseline: 4.4094x; 4.3927x over previous
#include <cuda_runtime.h>

#define B_   4
#define C_   256
#define CR_  32
#define N_   4096
#define EPS_ 1e-5f
#define SEXP_ 0.25503486f   // (1/sqrt(32)) * log2(e)

// ---------------- scratch (device globals; no allocations) ----------------
__device__ float g_q [B_*CR_*N_];
__device__ float g_k [B_*CR_*N_];
__device__ float g_v [B_*C_*N_];
__device__ float g_ao[B_*C_*N_];
__device__ float g_y [B_*C_*N_];

// ---------------- helpers ----------------
__device__ __forceinline__ unsigned tf32r(float x){
    unsigned r; asm("cvt.rna.tf32.f32 %0, %1;" : "=r"(r) : "f"(x)); return r;
}
__device__ __forceinline__ float tf32f(float x){ return __uint_as_float(tf32r(x)); }
__device__ __forceinline__ float ex2(float x){
    float r; asm("ex2.approx.f32 %0, %1;" : "=f"(r) : "f"(x)); return r;
}
__device__ __forceinline__ void mma8(float* d, const unsigned* a, const unsigned* b){
    asm volatile("mma.sync.aligned.m16n8k8.row.col.f32.tf32.tf32.f32 "
        "{%0,%1,%2,%3},{%4,%5,%6,%7},{%8,%9},{%0,%1,%2,%3};"
        : "+f"(d[0]), "+f"(d[1]), "+f"(d[2]), "+f"(d[3])
        : "r"(a[0]), "r"(a[1]), "r"(a[2]), "r"(a[3]), "r"(b[0]), "r"(b[1]));
}
__device__ __forceinline__ void cp16(unsigned daddr, const void* src){
    asm volatile("cp.async.cg.shared.global [%0], [%1], 16;" :: "r"(daddr), "l"(src));
}
__device__ __forceinline__ void cpcommit(){ asm volatile("cp.async.commit_group;"); }
template<int n> __device__ __forceinline__ void cpwait(){
    asm volatile("cp.async.wait_group %0;" :: "n"(n));
}

// ============================================================================
// Channel GEMM: Y[b,o,n] = sum_c W[o,c] * X[b,c,n]   (K = 256 always)
// CTA: 64o x 128n, 256 threads (8 warps, 2m x 4n), K chunks of 32, X double-buf.
// ============================================================================
#define GWS 260                    // ws row stride (floats)
#define GXS 132                    // xs row stride (floats)
#define GXO (64*GWS)               // xs offset (floats)
#define GXBUF (32*GXS)             // per-buffer floats
#define GEMM_SMEM ((GXO + 2*GXBUF)*4)

__global__ __launch_bounds__(256, 2) void gemm_mma(const float* __restrict__ W,
                                                   const float* __restrict__ X,
                                                   float* __restrict__ Y,
                                                   int OC, int round_out)
{
    extern __shared__ float sm[];
    unsigned* smu = (unsigned*)sm;
    unsigned sbase = (unsigned)__cvta_generic_to_shared(sm);

    const int tid = threadIdx.x, lane = tid & 31, wid = tid >> 5;
    const int g = lane >> 2, t = lane & 3;
    const int mw = wid >> 2, nw = wid & 3;     // warp tile: 32o x 32n
    const int n0 = blockIdx.x * 128;
    const int o0 = blockIdx.y * 64;
    const int b  = blockIdx.z;
    const float* Xb = X + (size_t)b * C_ * N_;

    // ---- stage W tile [64][256] with RNA-tf32 rounding (zero-fill o >= OC) ----
#pragma unroll
    for (int s = 0; s < 16; s++) {
        int u = tid + 256 * s;              // 4096 float4 units
        int o = u >> 6, c4 = (u & 63) * 4;
        float4 w4 = make_float4(0.f, 0.f, 0.f, 0.f);
        if (o0 + o < OC) w4 = *(const float4*)&W[(size_t)(o0 + o) * C_ + c4];
        w4.x = tf32f(w4.x); w4.y = tf32f(w4.y); w4.z = tf32f(w4.z); w4.w = tf32f(w4.w);
        *(float4*)&sm[o * GWS + c4] = w4;
    }

    // ---- X chunk loader (cp.async) ----
    auto loadX = [&](int kc, int bf) {
#pragma unroll
        for (int s = 0; s < 4; s++) {
            int u = tid + 256 * s;          // 1024 float4 units: 32 rows x 128
            int c = u >> 5, n4 = (u & 31) * 4;
            cp16(sbase + (GXO + bf * GXBUF + c * GXS + n4) * 4,
                 &Xb[(size_t)(kc * 32 + c) * N_ + n0 + n4]);
        }
    };

    float acc[2][4][4];
#pragma unroll
    for (int i = 0; i < 2; i++)
#pragma unroll
        for (int j = 0; j < 4; j++)
#pragma unroll
            for (int e = 0; e < 4; e++) acc[i][j][e] = 0.f;

    loadX(0, 0); cpcommit();

    for (int kc = 0; kc < 8; kc++) {
        int bf = kc & 1;
        if (kc < 7) { loadX(kc + 1, bf ^ 1); cpcommit(); cpwait<1>(); }
        else        { cpwait<0>(); }
        __syncthreads();

        const int xb = GXO + bf * GXBUF;
        const int wcol = kc * 32;           // <-- K-chunk offset into the W tile
#pragma unroll
        for (int k = 0; k < 4; k++) {
            int kk = 8 * k;
            unsigned a[2][4];
#pragma unroll
            for (int mt = 0; mt < 2; mt++) {
                int orow = 32 * mw + 16 * mt;
                a[mt][0] = smu[(orow + g)     * GWS + wcol + kk + t];
                a[mt][1] = smu[(orow + g + 8) * GWS + wcol + kk + t];
                a[mt][2] = smu[(orow + g)     * GWS + wcol + kk + t + 4];
                a[mt][3] = smu[(orow + g + 8) * GWS + wcol + kk + t + 4];
            }
#pragma unroll
            for (int nt = 0; nt < 4; nt++) {
                int nn = 32 * nw + 8 * nt;
                unsigned bb[2];
                bb[0] = smu[xb + (kk + t)     * GXS + nn + g];
                bb[1] = smu[xb + (kk + t + 4) * GXS + nn + g];
                mma8(acc[0][nt], a[0], bb);
                mma8(acc[1][nt], a[1], bb);
            }
        }
        __syncthreads();
    }

    // ---- epilogue ----
#pragma unroll
    for (int mt = 0; mt < 2; mt++) {
        int orow = o0 + 32 * mw + 16 * mt;
#pragma unroll
        for (int nt = 0; nt < 4; nt++) {
            int col = n0 + 32 * nw + 8 * nt + 2 * t;
            float e0 = acc[mt][nt][0], e1 = acc[mt][nt][1];
            float e2 = acc[mt][nt][2], e3 = acc[mt][nt][3];
            if (round_out) { e0 = tf32f(e0); e1 = tf32f(e1); e2 = tf32f(e2); e3 = tf32f(e3); }
            if (orow + g < OC)
                *(float2*)&Y[((size_t)b * OC + orow + g) * N_ + col] = make_float2(e0, e1);
            if (orow + g + 8 < OC)
                *(float2*)&Y[((size_t)b * OC + orow + g + 8) * N_ + col] = make_float2(e2, e3);
        }
    }
}

// ============================================================================
// Attention: one CTA per (128-query tile, batch), all 256 channels.
// 512 threads (16 warps). tf32 mma for S and PV. No-max softmax (logits~N(0,1)),
// deterministic denominators. K/V tiles double-buffered via cp.async.
// ============================================================================
#define QS_  0                     // [128][36] q-major
#define KS_  4608                  // 2 x [32][72]
#define KBUF 2304
#define PS_  9216                  // [128][68]
#define VS_  17920                 // 2 x [256][68]
#define VBUF 17408
#define OS_  17920                 // overlay on VS: [256][132]
#define LP_  52736                 // [128][2]
#define LS_  52992                 // [128]
#define ATTN_SMEM (53120*4)

__global__ __launch_bounds__(512, 1) void attn_mma()
{
    extern __shared__ float sm[];
    unsigned* smu = (unsigned*)sm;
    unsigned sbase = (unsigned)__cvta_generic_to_shared(sm);

    const int tid = threadIdx.x, lane = tid & 31, wid = tid >> 5;
    const int g = lane >> 2, t = lane & 3;
    const int q0 = blockIdx.x * 128;
    const int b  = blockIdx.y;
    // S-phase roles
    const int mq = wid >> 1, nh = wid & 1;
    // PV-phase roles
    const int qw = wid >> 2, cw = wid & 3;

    // ---- prologue: transpose-load Q tile -> qs[q][c] ----
#pragma unroll
    for (int s = 0; s < 2; s++) {
        int u = tid + 512 * s;               // 1024 units: 32c x 32(q/4)
        int c = u >> 5, q4 = (u & 31) * 4;
        float4 f = *(const float4*)&g_q[((size_t)b * CR_ + c) * N_ + q0 + q4];
        sm[QS_ + (q4 + 0) * 36 + c] = f.x;
        sm[QS_ + (q4 + 1) * 36 + c] = f.y;
        sm[QS_ + (q4 + 2) * 36 + c] = f.z;
        sm[QS_ + (q4 + 3) * 36 + c] = f.w;
    }
    if (tid < 128) sm[LS_ + tid] = 0.f;

    auto loadKV = [&](int jt, int bf) {
        int j0 = jt * 64;
        {   // K: 32 rows x 64 floats = 512 float4 units
            int c = tid >> 4, j4 = (tid & 15) * 4;
            cp16(sbase + (KS_ + bf * KBUF + c * 72 + j4) * 4,
                 &g_k[((size_t)b * CR_ + c) * N_ + j0 + j4]);
        }
#pragma unroll
        for (int s = 0; s < 8; s++) {        // V: 256 rows x 64 floats = 4096 units
            int u = tid + 512 * s;
            int c = u >> 4, j4 = (u & 15) * 4;
            cp16(sbase + (VS_ + bf * VBUF + c * 68 + j4) * 4,
                 &g_v[((size_t)b * C_ + c) * N_ + j0 + j4]);
        }
    };

    float oacc[2][8][4];
#pragma unroll
    for (int i = 0; i < 2; i++)
#pragma unroll
        for (int j = 0; j < 8; j++)
#pragma unroll
            for (int e = 0; e < 4; e++) oacc[i][j][e] = 0.f;

    loadKV(0, 0); cpcommit();

    for (int jt = 0; jt < N_ / 64; jt++) {
        int bf = jt & 1;
        if (jt + 1 < N_ / 64) { loadKV(jt + 1, bf ^ 1); cpcommit(); cpwait<1>(); }
        else                  { cpwait<0>(); }
        __syncthreads();   // K/V(bf) ready; prev S-phase consumers done

        // ---------------- S = Q^T K, p = exp2(S*SEXP) ----------------
        {
            const int kb = KS_ + bf * KBUF;
            float p[4][4];
#pragma unroll
            for (int nt = 0; nt < 4; nt++)
#pragma unroll
                for (int e = 0; e < 4; e++) p[nt][e] = 0.f;

#pragma unroll
            for (int k = 0; k < 4; k++) {
                int kk = 8 * k;
                unsigned a[4];
                int qrow = 16 * mq;
                a[0] = smu[QS_ + (qrow + g)     * 36 + kk + t];
                a[1] = smu[QS_ + (qrow + g + 8) * 36 + kk + t];
                a[2] = smu[QS_ + (qrow + g)     * 36 + kk + t + 4];
                a[3] = smu[QS_ + (qrow + g + 8) * 36 + kk + t + 4];
#pragma unroll
                for (int nt = 0; nt < 4; nt++) {
                    int jj = 32 * nh + 8 * nt;
                    unsigned bb[2];
                    bb[0] = smu[kb + (kk + t)     * 72 + jj + g];
                    bb[1] = smu[kb + (kk + t + 4) * 72 + jj + g];
                    mma8(p[nt], a, bb);
                }
            }
            float rs0 = 0.f, rs1 = 0.f;
            int qg = 16 * mq + g;
#pragma unroll
            for (int nt = 0; nt < 4; nt++) {
                int jj = 32 * nh + 8 * nt + 2 * t;
                float e0 = tf32f(ex2(p[nt][0] * SEXP_));
                float e1 = tf32f(ex2(p[nt][1] * SEXP_));
                float e2 = tf32f(ex2(p[nt][2] * SEXP_));
                float e3 = tf32f(ex2(p[nt][3] * SEXP_));
                rs0 += e0 + e1; rs1 += e2 + e3;
                *(float2*)&sm[PS_ + qg       * 68 + jj] = make_float2(e0, e1);
                *(float2*)&sm[PS_ + (qg + 8) * 68 + jj] = make_float2(e2, e3);
            }
            rs0 += __shfl_xor_sync(0xffffffffu, rs0, 1);
            rs0 += __shfl_xor_sync(0xffffffffu, rs0, 2);
            rs1 += __shfl_xor_sync(0xffffffffu, rs1, 1);
            rs1 += __shfl_xor_sync(0xffffffffu, rs1, 2);
            if (t == 0) {
                sm[LP_ + qg       * 2 + nh] = rs0;
                sm[LP_ + (qg + 8) * 2 + nh] = rs1;
            }
        }
        __syncthreads();   // ps + lpart ready

        if (tid < 128) sm[LS_ + tid] += sm[LP_ + 2 * tid] + sm[LP_ + 2 * tid + 1];

        // ---------------- O += P V^T ----------------
        {
            const int vb = VS_ + bf * VBUF;
            const int qa = 32 * qw;
#pragma unroll
            for (int k = 0; k < 8; k++) {
                int kk = 8 * k;
                unsigned a0[4], a1[4];
                a0[0] = smu[PS_ + (qa + g)      * 68 + kk + t];
                a0[1] = smu[PS_ + (qa + g + 8)  * 68 + kk + t];
                a0[2] = smu[PS_ + (qa + g)      * 68 + kk + t + 4];
                a0[3] = smu[PS_ + (qa + g + 8)  * 68 + kk + t + 4];
                a1[0] = smu[PS_ + (qa + g + 16) * 68 + kk + t];
                a1[1] = smu[PS_ + (qa + g + 24) * 68 + kk + t];
                a1[2] = smu[PS_ + (qa + g + 16) * 68 + kk + t + 4];
                a1[3] = smu[PS_ + (qa + g + 24) * 68 + kk + t + 4];
#pragma unroll
                for (int nt = 0; nt < 8; nt++) {
                    int cc = 64 * cw + 8 * nt;
                    unsigned bb[2];
                    bb[0] = smu[vb + (cc + g) * 68 + kk + t];
                    bb[1] = smu[vb + (cc + g) * 68 + kk + t + 4];
                    mma8(oacc[0][nt], a0, bb);
                    mma8(oacc[1][nt], a1, bb);
                }
            }
        }
        __syncthreads();   // PV done reading V(bf)/PS before next loadKV overwrites
    }

    if (tid < 128) sm[LS_ + tid] = 1.f / sm[LS_ + tid];
    __syncthreads();

    // ---- scale + transpose through smem (overlay on VS), coalesced store ----
#pragma unroll
    for (int mt = 0; mt < 2; mt++) {
        int row0 = 32 * qw + 16 * mt + g;
        float inv0 = sm[LS_ + row0];
        float inv1 = sm[LS_ + row0 + 8];
#pragma unroll
        for (int nt = 0; nt < 8; nt++) {
            int cc = 64 * cw + 8 * nt + 2 * t;
            sm[OS_ + cc       * 132 + row0]     = tf32f(oacc[mt][nt][0] * inv0);
            sm[OS_ + (cc + 1) * 132 + row0]     = tf32f(oacc[mt][nt][1] * inv0);
            sm[OS_ + cc       * 132 + row0 + 8] = tf32f(oacc[mt][nt][2] * inv1);
            sm[OS_ + (cc + 1) * 132 + row0 + 8] = tf32f(oacc[mt][nt][3] * inv1);
        }
    }
    __syncthreads();
#pragma unroll
    for (int s = 0; s < 16; s++) {
        int u = tid + 512 * s;                // 8192 float4 units: 256c x 32(q/4)
        int c = u >> 5, q4 = (u & 31) * 4;
        float4 f = *(const float4*)&sm[OS_ + c * 132 + q4];
        *(float4*)&g_ao[((size_t)b * C_ + c) * N_ + q0 + q4] = f;
    }
}

// ---------------- instance norm + residual ----------------
__global__ __launch_bounds__(256) void norm_kernel(const float* __restrict__ x1,
                                                   float* __restrict__ out)
{
    int row = blockIdx.x;                 // b*C + o
    const float* yr = g_y + (size_t)row * N_;
    const float* xr = x1  + (size_t)row * N_;
    float*       orow = out + (size_t)row * N_;
    int tid = threadIdx.x;

    float4 v[4];
    float s = 0.f, ss = 0.f;
#pragma unroll
    for (int k = 0; k < 4; k++) {
        v[k] = *(const float4*)&yr[(tid + 256 * k) * 4];
        s  += v[k].x + v[k].y + v[k].z + v[k].w;
        ss += v[k].x * v[k].x + v[k].y * v[k].y + v[k].z * v[k].z + v[k].w * v[k].w;
    }
#pragma unroll
    for (int o = 16; o; o >>= 1) {
        s  += __shfl_xor_sync(0xffffffffu, s,  o);
        ss += __shfl_xor_sync(0xffffffffu, ss, o);
    }
    __shared__ float rs[8], rss[8];
    __shared__ float stats[2];
    if ((tid & 31) == 0) { rs[tid >> 5] = s; rss[tid >> 5] = ss; }
    __syncthreads();
    if (tid < 32) {
        float a  = (tid < 8) ? rs[tid]  : 0.f;
        float b2 = (tid < 8) ? rss[tid] : 0.f;
#pragma unroll
        for (int o = 4; o; o >>= 1) {
            a  += __shfl_xor_sync(0xffffffffu, a,  o);
            b2 += __shfl_xor_sync(0xffffffffu, b2, o);
        }
        if (tid == 0) {
            float mean = a * (1.f / N_);
            float var  = b2 * (1.f / N_) - mean * mean;
            stats[0] = mean;
            stats[1] = rsqrtf(var + EPS_);
        }
    }
    __syncthreads();
    float mean = stats[0], inv = stats[1];
#pragma unroll
    for (int k = 0; k < 4; k++) {
        float4 x4 = *(const float4*)&xr[(tid + 256 * k) * 4];
        float4 o4;
        o4.x = (v[k].x - mean) * inv + x4.x;
        o4.y = (v[k].y - mean) * inv + x4.y;
        o4.z = (v[k].z - mean) * inv + x4.z;
        o4.w = (v[k].w - mean) * inv + x4.w;
        *(float4*)&orow[(tid + 256 * k) * 4] = o4;
    }
}

// ---------------- launcher ----------------
extern "C" void kernel_launch(void* const* d_in, const int* in_sizes, int n_in,
                              void* d_out, int out_size)
{
    (void)in_sizes; (void)n_in; (void)out_size;
    const float* x1 = (const float*)d_in[0];
    const float* x2 = (const float*)d_in[1];
    const float* wq = (const float*)d_in[2];
    const float* wk = (const float*)d_in[3];
    const float* wv = (const float*)d_in[4];
    const float* wp = (const float*)d_in[5];
    float* out = (float*)d_out;

    void *qp, *kp, *vp, *aop, *yp;
    cudaGetSymbolAddress(&qp,  g_q);
    cudaGetSymbolAddress(&kp,  g_k);
    cudaGetSymbolAddress(&vp,  g_v);
    cudaGetSymbolAddress(&aop, g_ao);
    cudaGetSymbolAddress(&yp,  g_y);

    cudaFuncSetAttribute(gemm_mma, cudaFuncAttributeMaxDynamicSharedMemorySize, GEMM_SMEM);
    cudaFuncSetAttribute(attn_mma, cudaFuncAttributeMaxDynamicSharedMemorySize, ATTN_SMEM);

    gemm_mma<<<dim3(N_/128, 1, B_), 256, GEMM_SMEM>>>(wq, x1, (float*)qp, CR_, 1);
    gemm_mma<<<dim3(N_/128, 1, B_), 256, GEMM_SMEM>>>(wk, x2, (float*)kp, CR_, 1);
    gemm_mma<<<dim3(N_/128, C_/64, B_), 256, GEMM_SMEM>>>(wv, x2, (float*)vp, C_, 1);
    attn_mma<<<dim3(N_/128, B_), 512, ATTN_SMEM>>>();
    gemm_mma<<<dim3(N_/128, C_/64, B_), 256, GEMM_SMEM>>>(wp, (const float*)aop, (float*)yp, C_, 0);
    norm_kernel<<<B_*C_, 256>>>(x1, out);
}

// round 6
// speedup vs baseline: 4.7610x; 1.0797x over previous
#include <cuda_runtime.h>

#define B_   4
#define C_   256
#define CR_  32
#define N_   4096
#define EPS_ 1e-5f
#define SEXP_ 0.25503486f   // (1/sqrt(32)) * log2(e)

// ---------------- scratch (device globals; no allocations) ----------------
__device__ float g_q [B_*CR_*N_];
__device__ float g_k [B_*CR_*N_];
__device__ float g_v [B_*C_*N_];
__device__ float g_ao[B_*C_*N_];
__device__ float g_y [B_*C_*N_];

// ---------------- helpers ----------------
__device__ __forceinline__ unsigned tf32r(float x){
    unsigned r; asm("cvt.rna.tf32.f32 %0, %1;" : "=r"(r) : "f"(x)); return r;
}
__device__ __forceinline__ float tf32f(float x){ return __uint_as_float(tf32r(x)); }
__device__ __forceinline__ float ex2(float x){
    float r; asm("ex2.approx.f32 %0, %1;" : "=f"(r) : "f"(x)); return r;
}
__device__ __forceinline__ void mma8(float* d, const unsigned* a, const unsigned* b){
    asm volatile("mma.sync.aligned.m16n8k8.row.col.f32.tf32.tf32.f32 "
        "{%0,%1,%2,%3},{%4,%5,%6,%7},{%8,%9},{%0,%1,%2,%3};"
        : "+f"(d[0]), "+f"(d[1]), "+f"(d[2]), "+f"(d[3])
        : "r"(a[0]), "r"(a[1]), "r"(a[2]), "r"(a[3]), "r"(b[0]), "r"(b[1]));
}
__device__ __forceinline__ void cp16(unsigned daddr, const void* src){
    asm volatile("cp.async.cg.shared.global [%0], [%1], 16;" :: "r"(daddr), "l"(src));
}
__device__ __forceinline__ void cpcommit(){ asm volatile("cp.async.commit_group;"); }
template<int n> __device__ __forceinline__ void cpwait(){
    asm volatile("cp.async.wait_group %0;" :: "n"(n));
}

// ============================================================================
// Channel GEMM: Y[b,o,n] = sum_c W[o,c] * X[b,c,n]   (K = 256 always)
// CTA: 64o x 128n, 256 threads (8 warps, 2m x 4n), K chunks of 32, X double-buf.
// ============================================================================
#define GWS 260
#define GXS 132
#define GXO (64*GWS)
#define GXBUF (32*GXS)
#define GEMM_SMEM ((GXO + 2*GXBUF)*4)

__global__ __launch_bounds__(256, 2) void gemm_mma(const float* __restrict__ W,
                                                   const float* __restrict__ X,
                                                   float* __restrict__ Y,
                                                   int OC, int round_out)
{
    extern __shared__ float sm[];
    unsigned* smu = (unsigned*)sm;
    unsigned sbase = (unsigned)__cvta_generic_to_shared(sm);

    const int tid = threadIdx.x, lane = tid & 31, wid = tid >> 5;
    const int g = lane >> 2, t = lane & 3;
    const int mw = wid >> 2, nw = wid & 3;
    const int n0 = blockIdx.x * 128;
    const int o0 = blockIdx.y * 64;
    const int b  = blockIdx.z;
    const float* Xb = X + (size_t)b * C_ * N_;

#pragma unroll
    for (int s = 0; s < 16; s++) {
        int u = tid + 256 * s;
        int o = u >> 6, c4 = (u & 63) * 4;
        float4 w4 = make_float4(0.f, 0.f, 0.f, 0.f);
        if (o0 + o < OC) w4 = *(const float4*)&W[(size_t)(o0 + o) * C_ + c4];
        w4.x = tf32f(w4.x); w4.y = tf32f(w4.y); w4.z = tf32f(w4.z); w4.w = tf32f(w4.w);
        *(float4*)&sm[o * GWS + c4] = w4;
    }

    auto loadX = [&](int kc, int bf) {
#pragma unroll
        for (int s = 0; s < 4; s++) {
            int u = tid + 256 * s;
            int c = u >> 5, n4 = (u & 31) * 4;
            cp16(sbase + (GXO + bf * GXBUF + c * GXS + n4) * 4,
                 &Xb[(size_t)(kc * 32 + c) * N_ + n0 + n4]);
        }
    };

    float acc[2][4][4];
#pragma unroll
    for (int i = 0; i < 2; i++)
#pragma unroll
        for (int j = 0; j < 4; j++)
#pragma unroll
            for (int e = 0; e < 4; e++) acc[i][j][e] = 0.f;

    loadX(0, 0); cpcommit();

    for (int kc = 0; kc < 8; kc++) {
        int bf = kc & 1;
        if (kc < 7) { loadX(kc + 1, bf ^ 1); cpcommit(); cpwait<1>(); }
        else        { cpwait<0>(); }
        __syncthreads();

        const int xb = GXO + bf * GXBUF;
        const int wcol = kc * 32;
#pragma unroll
        for (int k = 0; k < 4; k++) {
            int kk = 8 * k;
            unsigned a[2][4];
#pragma unroll
            for (int mt = 0; mt < 2; mt++) {
                int orow = 32 * mw + 16 * mt;
                a[mt][0] = smu[(orow + g)     * GWS + wcol + kk + t];
                a[mt][1] = smu[(orow + g + 8) * GWS + wcol + kk + t];
                a[mt][2] = smu[(orow + g)     * GWS + wcol + kk + t + 4];
                a[mt][3] = smu[(orow + g + 8) * GWS + wcol + kk + t + 4];
            }
#pragma unroll
            for (int nt = 0; nt < 4; nt++) {
                int nn = 32 * nw + 8 * nt;
                unsigned bb[2];
                bb[0] = smu[xb + (kk + t)     * GXS + nn + g];
                bb[1] = smu[xb + (kk + t + 4) * GXS + nn + g];
                mma8(acc[0][nt], a[0], bb);
                mma8(acc[1][nt], a[1], bb);
            }
        }
        __syncthreads();
    }

#pragma unroll
    for (int mt = 0; mt < 2; mt++) {
        int orow = o0 + 32 * mw + 16 * mt;
#pragma unroll
        for (int nt = 0; nt < 4; nt++) {
            int col = n0 + 32 * nw + 8 * nt + 2 * t;
            float e0 = acc[mt][nt][0], e1 = acc[mt][nt][1];
            float e2 = acc[mt][nt][2], e3 = acc[mt][nt][3];
            if (round_out) { e0 = tf32f(e0); e1 = tf32f(e1); e2 = tf32f(e2); e3 = tf32f(e3); }
            if (orow + g < OC)
                *(float2*)&Y[((size_t)b * OC + orow + g) * N_ + col] = make_float2(e0, e1);
            if (orow + g + 8 < OC)
                *(float2*)&Y[((size_t)b * OC + orow + g + 8) * N_ + col] = make_float2(e2, e3);
        }
    }
}

// ============================================================================
// Attention: CTA = (128 q) x (all 256 c) per batch. 256 threads / 8 warps.
// S-phase warp tile 32q x 32j; PV warp tile 64q x 64c (128 acc regs/thread).
// 2 barriers per j-tile; lsum in registers; K/V double-buffered cp.async.
// ============================================================================
#define QS_  0                       // [128][36]
#define KS_  4608                    // 2 x [32][68]
#define KBUF 2176
#define PS_  8960                    // [128][68]
#define VS_  17664                   // 2 x [256][68]
#define VBUF 17408
#define OS_  17664                   // overlay on VS: [256][132]
#define LP_  52480                   // [128][2]
#define LS_  52736                   // [128]
#define ATTN_SMEM (52864*4)

__global__ __launch_bounds__(256, 1) void attn_mma()
{
    extern __shared__ float sm[];
    unsigned* smu = (unsigned*)sm;
    unsigned sbase = (unsigned)__cvta_generic_to_shared(sm);

    const int tid = threadIdx.x, lane = tid & 31, wid = tid >> 5;
    const int g = lane >> 2, t = lane & 3;
    const int q0 = blockIdx.x * 128;
    const int b  = blockIdx.y;
    // S-phase roles: 4 q-blocks x 2 j-halves
    const int mq = wid & 3, nh = wid >> 2;
    const int qrow = 32 * mq;
    // PV-phase roles: 2 q-halves x 4 c-blocks
    const int qw = wid & 1, cw = wid >> 1;

    // ---- prologue: transpose-load Q tile -> qs[q][c] ----
#pragma unroll
    for (int s = 0; s < 4; s++) {
        int u = tid + 256 * s;               // 1024 units: 32c x 32(q/4)
        int c = u >> 5, q4 = (u & 31) * 4;
        float4 f = *(const float4*)&g_q[((size_t)b * CR_ + c) * N_ + q0 + q4];
        sm[QS_ + (q4 + 0) * 36 + c] = f.x;
        sm[QS_ + (q4 + 1) * 36 + c] = f.y;
        sm[QS_ + (q4 + 2) * 36 + c] = f.z;
        sm[QS_ + (q4 + 3) * 36 + c] = f.w;
    }

    auto loadKV = [&](int jt, int bf) {
        int j0 = jt * 64;
#pragma unroll
        for (int s = 0; s < 2; s++) {        // K: 512 float4 units
            int u = tid + 256 * s;
            int c = u >> 4, j4 = (u & 15) * 4;
            cp16(sbase + (KS_ + bf * KBUF + c * 68 + j4) * 4,
                 &g_k[((size_t)b * CR_ + c) * N_ + j0 + j4]);
        }
#pragma unroll
        for (int s = 0; s < 16; s++) {       // V: 4096 float4 units
            int u = tid + 256 * s;
            int c = u >> 4, j4 = (u & 15) * 4;
            cp16(sbase + (VS_ + bf * VBUF + c * 68 + j4) * 4,
                 &g_v[((size_t)b * C_ + c) * N_ + j0 + j4]);
        }
    };

    float oacc[4][8][4];
#pragma unroll
    for (int i = 0; i < 4; i++)
#pragma unroll
        for (int j = 0; j < 8; j++)
#pragma unroll
            for (int e = 0; e < 4; e++) oacc[i][j][e] = 0.f;

    float lreg[2][2] = {{0.f, 0.f}, {0.f, 0.f}};   // [m-tile][row-half] running denominators

    loadKV(0, 0); cpcommit();

    for (int jt = 0; jt < N_ / 64; jt++) {
        const int bf = jt & 1;
        cpwait<0>();
        __syncthreads();   // KV(bf) visible; PV(jt-1)/S(jt-1) done with buffers bf^1 and PS

        if (jt + 1 < N_ / 64) { loadKV(jt + 1, bf ^ 1); cpcommit(); }

        // ---------------- S = Q^T K, p = exp2(S*SEXP) -> PS ----------------
        {
            const int kb = KS_ + bf * KBUF;
            float sacc[2][4][4];
#pragma unroll
            for (int mt = 0; mt < 2; mt++)
#pragma unroll
                for (int nt = 0; nt < 4; nt++)
#pragma unroll
                    for (int e = 0; e < 4; e++) sacc[mt][nt][e] = 0.f;

#pragma unroll
            for (int k = 0; k < 4; k++) {
                int kk = 8 * k;
                unsigned a[2][4];
#pragma unroll
                for (int mt = 0; mt < 2; mt++) {
                    int r = qrow + 16 * mt;
                    a[mt][0] = smu[QS_ + (r + g)     * 36 + kk + t];
                    a[mt][1] = smu[QS_ + (r + g + 8) * 36 + kk + t];
                    a[mt][2] = smu[QS_ + (r + g)     * 36 + kk + t + 4];
                    a[mt][3] = smu[QS_ + (r + g + 8) * 36 + kk + t + 4];
                }
#pragma unroll
                for (int nt = 0; nt < 4; nt++) {
                    int jj = 32 * nh + 8 * nt;
                    unsigned bb[2];
                    bb[0] = smu[kb + (kk + t)     * 68 + jj + g];
                    bb[1] = smu[kb + (kk + t + 4) * 68 + jj + g];
                    mma8(sacc[0][nt], a[0], bb);
                    mma8(sacc[1][nt], a[1], bb);
                }
            }
#pragma unroll
            for (int mt = 0; mt < 2; mt++) {
                int r = qrow + 16 * mt;
#pragma unroll
                for (int nt = 0; nt < 4; nt++) {
                    int jj = 32 * nh + 8 * nt + 2 * t;
                    float e0 = tf32f(ex2(sacc[mt][nt][0] * SEXP_));
                    float e1 = tf32f(ex2(sacc[mt][nt][1] * SEXP_));
                    float e2 = tf32f(ex2(sacc[mt][nt][2] * SEXP_));
                    float e3 = tf32f(ex2(sacc[mt][nt][3] * SEXP_));
                    lreg[mt][0] += e0 + e1;
                    lreg[mt][1] += e2 + e3;
                    *(float2*)&sm[PS_ + (r + g)     * 68 + jj] = make_float2(e0, e1);
                    *(float2*)&sm[PS_ + (r + g + 8) * 68 + jj] = make_float2(e2, e3);
                }
            }
        }
        __syncthreads();   // PS ready

        // ---------------- O += P V^T ----------------
        {
            const int vb = VS_ + bf * VBUF;
#pragma unroll
            for (int k = 0; k < 8; k++) {
                int kk = 8 * k;
                unsigned a[4][4];
#pragma unroll
                for (int mt = 0; mt < 4; mt++) {
                    int r = 64 * qw + 16 * mt;
                    a[mt][0] = smu[PS_ + (r + g)     * 68 + kk + t];
                    a[mt][1] = smu[PS_ + (r + g + 8) * 68 + kk + t];
                    a[mt][2] = smu[PS_ + (r + g)     * 68 + kk + t + 4];
                    a[mt][3] = smu[PS_ + (r + g + 8) * 68 + kk + t + 4];
                }
#pragma unroll
                for (int nt = 0; nt < 8; nt++) {
                    int cc = 64 * cw + 8 * nt;
                    unsigned bb[2];
                    bb[0] = smu[vb + (cc + g) * 68 + kk + t];
                    bb[1] = smu[vb + (cc + g) * 68 + kk + t + 4];
#pragma unroll
                    for (int mt = 0; mt < 4; mt++) mma8(oacc[mt][nt], a[mt], bb);
                }
            }
        }
        // next iteration's top barrier protects PS and V(bf) from overwrite
    }

    // ---- denominators: reduce register partials ----
    {
        float r0 = lreg[0][0], r1 = lreg[0][1], r2 = lreg[1][0], r3 = lreg[1][1];
        r0 += __shfl_xor_sync(0xffffffffu, r0, 1); r0 += __shfl_xor_sync(0xffffffffu, r0, 2);
        r1 += __shfl_xor_sync(0xffffffffu, r1, 1); r1 += __shfl_xor_sync(0xffffffffu, r1, 2);
        r2 += __shfl_xor_sync(0xffffffffu, r2, 1); r2 += __shfl_xor_sync(0xffffffffu, r2, 2);
        r3 += __shfl_xor_sync(0xffffffffu, r3, 1); r3 += __shfl_xor_sync(0xffffffffu, r3, 2);
        if (t == 0) {
            sm[LP_ + (qrow + g)      * 2 + nh] = r0;
            sm[LP_ + (qrow + g + 8)  * 2 + nh] = r1;
            sm[LP_ + (qrow + g + 16) * 2 + nh] = r2;
            sm[LP_ + (qrow + g + 24) * 2 + nh] = r3;
        }
    }
    __syncthreads();
    if (tid < 128) sm[LS_ + tid] = 1.f / (sm[LP_ + 2 * tid] + sm[LP_ + 2 * tid + 1]);
    __syncthreads();

    // ---- scale + transpose through smem (overlay on VS), coalesced store ----
#pragma unroll
    for (int mt = 0; mt < 4; mt++) {
        int row0 = 64 * qw + 16 * mt + g;
        float inv0 = sm[LS_ + row0];
        float inv1 = sm[LS_ + row0 + 8];
#pragma unroll
        for (int nt = 0; nt < 8; nt++) {
            int cc = 64 * cw + 8 * nt + 2 * t;
            sm[OS_ + cc       * 132 + row0]     = tf32f(oacc[mt][nt][0] * inv0);
            sm[OS_ + (cc + 1) * 132 + row0]     = tf32f(oacc[mt][nt][1] * inv0);
            sm[OS_ + cc       * 132 + row0 + 8] = tf32f(oacc[mt][nt][2] * inv1);
            sm[OS_ + (cc + 1) * 132 + row0 + 8] = tf32f(oacc[mt][nt][3] * inv1);
        }
    }
    __syncthreads();
#pragma unroll
    for (int s = 0; s < 32; s++) {
        int u = tid + 256 * s;               // 8192 float4 units: 256c x 32(q/4)
        int c = u >> 5, q4 = (u & 31) * 4;
        float4 f = *(const float4*)&sm[OS_ + c * 132 + q4];
        *(float4*)&g_ao[((size_t)b * C_ + c) * N_ + q0 + q4] = f;
    }
}

// ---------------- instance norm + residual ----------------
__global__ __launch_bounds__(256) void norm_kernel(const float* __restrict__ x1,
                                                   float* __restrict__ out)
{
    int row = blockIdx.x;
    const float* yr = g_y + (size_t)row * N_;
    const float* xr = x1  + (size_t)row * N_;
    float*       orow = out + (size_t)row * N_;
    int tid = threadIdx.x;

    float4 v[4];
    float s = 0.f, ss = 0.f;
#pragma unroll
    for (int k = 0; k < 4; k++) {
        v[k] = *(const float4*)&yr[(tid + 256 * k) * 4];
        s  += v[k].x + v[k].y + v[k].z + v[k].w;
        ss += v[k].x * v[k].x + v[k].y * v[k].y + v[k].z * v[k].z + v[k].w * v[k].w;
    }
#pragma unroll
    for (int o = 16; o; o >>= 1) {
        s  += __shfl_xor_sync(0xffffffffu, s,  o);
        ss += __shfl_xor_sync(0xffffffffu, ss, o);
    }
    __shared__ float rs[8], rss[8];
    __shared__ float stats[2];
    if ((tid & 31) == 0) { rs[tid >> 5] = s; rss[tid >> 5] = ss; }
    __syncthreads();
    if (tid < 32) {
        float a  = (tid < 8) ? rs[tid]  : 0.f;
        float b2 = (tid < 8) ? rss[tid] : 0.f;
#pragma unroll
        for (int o = 4; o; o >>= 1) {
            a  += __shfl_xor_sync(0xffffffffu, a,  o);
            b2 += __shfl_xor_sync(0xffffffffu, b2, o);
        }
        if (tid == 0) {
            float mean = a * (1.f / N_);
            float var  = b2 * (1.f / N_) - mean * mean;
            stats[0] = mean;
            stats[1] = rsqrtf(var + EPS_);
        }
    }
    __syncthreads();
    float mean = stats[0], inv = stats[1];
#pragma unroll
    for (int k = 0; k < 4; k++) {
        float4 x4 = *(const float4*)&xr[(tid + 256 * k) * 4];
        float4 o4;
        o4.x = (v[k].x - mean) * inv + x4.x;
        o4.y = (v[k].y - mean) * inv + x4.y;
        o4.z = (v[k].z - mean) * inv + x4.z;
        o4.w = (v[k].w - mean) * inv + x4.w;
        *(float4*)&orow[(tid + 256 * k) * 4] = o4;
    }
}

// ---------------- launcher ----------------
extern "C" void kernel_launch(void* const* d_in, const int* in_sizes, int n_in,
                              void* d_out, int out_size)
{
    (void)in_sizes; (void)n_in; (void)out_size;
    const float* x1 = (const float*)d_in[0];
    const float* x2 = (const float*)d_in[1];
    const float* wq = (const float*)d_in[2];
    const float* wk = (const float*)d_in[3];
    const float* wv = (const float*)d_in[4];
    const float* wp = (const float*)d_in[5];
    float* out = (float*)d_out;

    void *qp, *kp, *vp, *aop, *yp;
    cudaGetSymbolAddress(&qp,  g_q);
    cudaGetSymbolAddress(&kp,  g_k);
    cudaGetSymbolAddress(&vp,  g_v);
    cudaGetSymbolAddress(&aop, g_ao);
    cudaGetSymbolAddress(&yp,  g_y);

    cudaFuncSetAttribute(gemm_mma, cudaFuncAttributeMaxDynamicSharedMemorySize, GEMM_SMEM);
    cudaFuncSetAttribute(attn_mma, cudaFuncAttributeMaxDynamicSharedMemorySize, ATTN_SMEM);

    gemm_mma<<<dim3(N_/128, 1, B_), 256, GEMM_SMEM>>>(wq, x1, (float*)qp, CR_, 1);
    gemm_mma<<<dim3(N_/128, 1, B_), 256, GEMM_SMEM>>>(wk, x2, (float*)kp, CR_, 1);
    gemm_mma<<<dim3(N_/128, C_/64, B_), 256, GEMM_SMEM>>>(wv, x2, (float*)vp, C_, 1);
    attn_mma<<<dim3(N_/128, B_), 256, ATTN_SMEM>>>();
    gemm_mma<<<dim3(N_/128, C_/64, B_), 256, GEMM_SMEM>>>(wp, (const float*)aop, (float*)yp, C_, 0);
    norm_kernel<<<B_*C_, 256>>>(x1, out);
}